// round 16
// baseline (speedup 1.0000x reference)
#include <cuda_runtime.h>
#include <cuda_fp16.h>
#include <math.h>
#include <stdint.h>

#define B_  2
#define S_  2048
#define E_  1024
#define H_  16
#define DH_ 64
#define BH_ (B_*H_)

// ---------------------------------------------------------------------------
// Global scratch (allocation-free rule). Zero-initialized at module load;
// cells never written stay zero on every replay (writes are deterministic).
// ---------------------------------------------------------------------------
__device__ __half    g_xh [(size_t)B_*S_*E_];           // x fp16, 16k-permuted [4096][1024]
__device__ uint32_t  g_wch[(size_t)64*3072*8];          // QKV W frag: [k16][n][8 words]
__device__ uint32_t  g_woh[(size_t)64*1024*8];          // wo frag:    [k16][n][8 words]
__device__ __half    g_qh [(size_t)BH_*S_*DH_];         // plain [bh][S][64], pre-scaled
__device__ __half    g_kpl[(size_t)BH_*S_*DH_];         // compact K plain [bh][pos][64]
__device__ __half    g_vtp[(size_t)BH_*DH_*S_];         // compact V transposed [bh][d][pos]
__device__ uint32_t  g_aoh[(size_t)B_*S_*512];          // attn out fp16 perm [4096][512w]
__device__ int       g_perm[(size_t)B_*S_];             // compact pos -> s
__device__ int       g_nv[B_];
__device__ float     g_cmask[(size_t)B_*S_];            // 0 or -1e9*log2e

// ---------------------------------------------------------------------------
// helpers
// ---------------------------------------------------------------------------
__device__ __forceinline__ int posf(int j) {            // 16-k block permutation
    return ((j & 6) + (j >> 3)) * 2 + (j & 1);
}

__device__ __forceinline__ void mma16(float& d0, float& d1, float& d2, float& d3,
                                      uint32_t a0, uint32_t a1, uint32_t a2, uint32_t a3,
                                      uint32_t b0, uint32_t b1) {
    asm volatile(
        "mma.sync.aligned.m16n8k16.row.col.f32.f16.f16.f32 "
        "{%0,%1,%2,%3}, {%4,%5,%6,%7}, {%8,%9}, {%0,%1,%2,%3};"
        : "+f"(d0), "+f"(d1), "+f"(d2), "+f"(d3)
        : "r"(a0), "r"(a1), "r"(a2), "r"(a3), "r"(b0), "r"(b1));
}

#define LDSM4(r0, r1, r2, r3, addr) \
    asm volatile("ldmatrix.sync.aligned.m8n8.x4.shared.b16 {%0,%1,%2,%3}, [%4];" \
        : "=r"(r0), "=r"(r1), "=r"(r2), "=r"(r3) : "r"(addr))

__device__ __forceinline__ void cpa16(uint32_t dst_smem, const void* src) {
    asm volatile("cp.async.cg.shared.global [%0], [%1], 16;\n"
                 :: "r"(dst_smem), "l"(src));
}
__device__ __forceinline__ void cp_commit() {
    asm volatile("cp.async.commit_group;\n");
}
template<int N> __device__ __forceinline__ void cp_wait() {
    asm volatile("cp.async.wait_group %0;\n" :: "n"(N));
}

__device__ __forceinline__ uint32_t h2u(__half2 h) {
    return *reinterpret_cast<uint32_t*>(&h);
}

// ---------------------------------------------------------------------------
// Mask scan: forward perm + nv + compact mask
// ---------------------------------------------------------------------------
__global__ __launch_bounds__(1024) void scan_mask(const int* __restrict__ mask) {
    __shared__ int buf[2][1024];
    const int b = blockIdx.x, t = threadIdx.x;
    const int m0 = mask[b * 2048 + 2 * t]     != 0;
    const int m1 = mask[b * 2048 + 2 * t + 1] != 0;
    const int sum = m0 + m1;
    buf[0][t] = sum;
    __syncthreads();
    int src = 0;
    for (int off = 1; off < 1024; off <<= 1) {
        int v = buf[src][t];
        if (t >= off) v += buf[src][t - off];
        buf[src ^ 1][t] = v;
        src ^= 1;
        __syncthreads();
    }
    const int incl = buf[src][t];
    const int nv   = buf[src][1023];
    const int excl = incl - sum;
    if (m0) g_perm[b * 2048 + excl]      = 2 * t;
    if (m1) g_perm[b * 2048 + excl + m0] = 2 * t + 1;
    if (t == 0) g_nv[b] = nv;
    const float MBv = -1.4426950408889634e9f;
    g_cmask[b * 2048 + 2 * t]     = (2 * t     < nv) ? 0.f : MBv;
    g_cmask[b * 2048 + 2 * t + 1] = (2 * t + 1 < nv) ? 0.f : MBv;
}

// ---------------------------------------------------------------------------
// Unified prep: blocks [0,1024) xh, [1024,1792) wc, [1792,2048) wo.
// ---------------------------------------------------------------------------
__global__ __launch_bounds__(256) void prep_all(
    const float* __restrict__ x,
    const float* __restrict__ wq, const float* __restrict__ wk,
    const float* __restrict__ wv, const float* __restrict__ wo)
{
    const int blk = blockIdx.x;
    const int tid = threadIdx.x;

    if (blk < 1024) {                                  // ---- x -> g_xh
        int i = blk * 256 + tid;
        int row = i >> 6, grp = i & 63;
        const float* s = x + (size_t)row * 1024 + grp * 16;
        float v[16];
#pragma unroll
        for (int j = 0; j < 4; j++) {
            float4 t = *(const float4*)(s + j * 4);
            v[j*4] = t.x; v[j*4+1] = t.y; v[j*4+2] = t.z; v[j*4+3] = t.w;
        }
        __align__(16) __half o[16];
#pragma unroll
        for (int j = 0; j < 16; j++) o[posf(j)] = __float2half_rn(v[j]);
        *(uint4*)(g_xh + (size_t)row * 1024 + grp * 16)     = ((uint4*)o)[0];
        *(uint4*)(g_xh + (size_t)row * 1024 + grp * 16 + 8) = ((uint4*)o)[1];
    } else if (blk < 1792) {                           // ---- qkv weights
        int i = (blk - 1024) * 256 + tid;              // i = k16*3072 + n
        int k16 = i / 3072;
        int n = i - k16 * 3072;
        int which = n >> 10;
        int h = (n >> 6) & 15;
        int d = n & 63;
        const float* w = (which == 0 ? wq : (which == 1 ? wk : wv))
                         + ((size_t)h * 1024 + k16 * 16) * 64 + d;
        __align__(16) __half o[16];
#pragma unroll
        for (int j = 0; j < 16; j++) o[posf(j)] = __float2half_rn(w[j * 64]);
        uint32_t* dst = g_wch + ((size_t)k16 * 3072 + n) * 8;
        *(uint4*)dst       = ((uint4*)o)[0];
        *(uint4*)(dst + 4) = ((uint4*)o)[1];
    } else {                                           // ---- wo
        int i = (blk - 1792) * 256 + tid;
        int k16 = i >> 10;
        int n = i & 1023;
        __align__(16) __half o[16];
#pragma unroll
        for (int j = 0; j < 16; j++)
            o[posf(j)] = __float2half_rn(wo[(size_t)(k16 * 16 + j) * 1024 + n]);
        uint32_t* dst = g_woh + ((size_t)k16 * 1024 + n) * 8;
        *(uint4*)dst       = ((uint4*)o)[0];
        *(uint4*)(dst + 4) = ((uint4*)o)[1];
    }
}

// ---------------------------------------------------------------------------
// GEMM mainloop (fp16): 128x128 tile, 256 threads (8 warps, warp tile 64x32),
// k-step 32 halves, 4-stage cp.async ring. A given as the thread's own row.
// ---------------------------------------------------------------------------
#define LDA 24
#define A_BUF (128*LDA)
#define B_BUF 2048
#define STAGE_WORDS (A_BUF + B_BUF)
#define GEMM_SMEM_BYTES (4 * STAGE_WORDS * 4)

extern __shared__ uint32_t dynsmem[];

__device__ __forceinline__ void gemm_main(
    const __half* __restrict__ Arow,
    const uint32_t* __restrict__ Bw,
    int nTot,
    float acc[4][4][4])
{
    const int tid  = threadIdx.x;
    const int warp = tid >> 5;
    const int lane = tid & 31;
    const int g    = lane >> 2;
    const int tig  = lane & 3;
    const int wm   = (warp >> 2) * 64;
    const int wn   = (warp & 3) * 32;

#pragma unroll
    for (int ms = 0; ms < 4; ms++)
#pragma unroll
        for (int nt = 0; nt < 4; nt++)
#pragma unroll
            for (int r = 0; r < 4; r++) acc[ms][nt][r] = 0.f;

    const uint32_t sm = (uint32_t)__cvta_generic_to_shared(dynsmem);

    const int arow = tid >> 1;
    const int apart = tid & 1;
    const int bblk = tid >> 7;
    const int bn   = tid & 127;

    auto copy_tile = [&](int k0, int st) {
        const uint32_t base = sm + (uint32_t)st * (STAGE_WORDS * 4);
        uint32_t dA = base + (uint32_t)arow * (LDA * 4) + (uint32_t)apart * 32;
        const __half* srcA = Arow + k0 + apart * 16;
        cpa16(dA, srcA);
        cpa16(dA + 16, srcA + 8);
        uint32_t dB = base + A_BUF * 4 + (uint32_t)(bblk * 1024 + bn * 8) * 4;
        const uint32_t* srcB = Bw + ((size_t)((k0 >> 4) + bblk) * nTot + bn) * 8;
        cpa16(dB, srcB);
        cpa16(dB + 16, srcB + 4);
        cp_commit();
    };

    copy_tile(0, 0);
    copy_tile(32, 1);
    copy_tile(64, 2);

    int st = 0;
#pragma unroll 1
    for (int k0 = 0; k0 < 1024; k0 += 32) {
        if (k0 + 64 < 1024)      cp_wait<2>();
        else if (k0 + 32 < 1024) cp_wait<1>();
        else                     cp_wait<0>();
        __syncthreads();
        if (k0 + 96 < 1024) {
            int nst = st + 3; if (nst >= 4) nst -= 4;
            copy_tile(k0 + 96, nst);
        }

        const uint32_t* A  = dynsmem + st * STAGE_WORDS;
        const uint32_t* Bt = A + A_BUF;
#pragma unroll
        for (int kk = 0; kk < 2; kk++) {
            uint32_t af[4][4];
#pragma unroll
            for (int ms = 0; ms < 4; ms++) {
                const uint32_t* ap = A + (wm + 16 * ms + g) * LDA + kk * 8 + 2 * tig;
                uint2 lo = *(const uint2*)ap;
                uint2 hi = *(const uint2*)(ap + 8 * LDA);
                af[ms][0] = lo.x; af[ms][1] = hi.x; af[ms][2] = lo.y; af[ms][3] = hi.y;
            }
#pragma unroll
            for (int nt = 0; nt < 4; nt++) {
                uint2 b = *(const uint2*)(Bt + kk * 1024 + (wn + 8 * nt + g) * 8 + 2 * tig);
#pragma unroll
                for (int ms = 0; ms < 4; ms++)
                    mma16(acc[ms][nt][0], acc[ms][nt][1], acc[ms][nt][2], acc[ms][nt][3],
                          af[ms][0], af[ms][1], af[ms][2], af[ms][3], b.x, b.y);
            }
        }
        st = (st + 1 == 4) ? 0 : st + 1;
    }
}

// ---------------------------------------------------------------------------
// Combined Q + KV projections in ONE launch. grid (32, 24), block 256.
// K written plain compacted; V written transposed compacted.
// ---------------------------------------------------------------------------
__global__ __launch_bounds__(256, 2) void qkv2_kernel(
    const float* __restrict__ bq, const float* __restrict__ bk,
    const float* __restrict__ bv)
{
    const int m0 = blockIdx.x * 128;
    const int ny = blockIdx.y;
    const int b  = m0 >> 11;
    const bool isQ = (ny < 8);

    const int nv = g_nv[b];
    if (!isQ) {
        const int npad128 = (nv + 127) & ~127;
        if ((m0 & 2047) >= npad128) return;
    }

    const int n0 = isQ ? ny * 128 : 1024 + (ny - 8) * 128;

    const int tid  = threadIdx.x;
    const __half* Arow;
    if (isQ) {
        Arow = g_xh + (size_t)(m0 + (tid >> 1)) * 1024;
    } else {
        const int p = (m0 & 2047) + (tid >> 1);
        const int srow = (p < nv) ? g_perm[b * 2048 + p] : 0;
        Arow = g_xh + ((size_t)b * 2048 + srow) * 1024;
    }

    float acc[4][4][4];
    gemm_main(Arow, g_wch + (size_t)n0 * 8, 3072, acc);

    const int warp = tid >> 5;
    const int lane = tid & 31;
    const int g    = lane >> 2;
    const int tig  = lane & 3;
    const int wm   = (warp >> 2) * 64;
    const int wn   = (warp & 3) * 32;

    const float SC = 0.18033688011112158f;   // (1/8) * log2(e)

#pragma unroll
    for (int ms = 0; ms < 4; ms++) {
#pragma unroll
        for (int nt = 0; nt < 4; nt++) {
            const int C = n0 + wn + 8 * nt + 2 * tig;
            const int h = (C >> 6) & 15;
            const int d = C & 63;
            const int bh = b * 16 + h;

            if (isQ) {
                const int r0 = m0 + wm + 16 * ms + g;
                const int s0 = r0 & 2047;
                const int s1 = s0 + 8;
                const float bx = __ldg(&bq[C]);
                const float by = __ldg(&bq[C + 1]);
                __half* dst = g_qh + (size_t)bh * S_ * 64;
                *(__half2*)(dst + (size_t)s0 * 64 + d) =
                    __floats2half2_rn((acc[ms][nt][0] + bx) * SC,
                                      (acc[ms][nt][1] + by) * SC);
                *(__half2*)(dst + (size_t)s1 * 64 + d) =
                    __floats2half2_rn((acc[ms][nt][2] + bx) * SC,
                                      (acc[ms][nt][3] + by) * SC);
            } else {
                const int p0 = (m0 & 2047) + wm + 16 * ms + g;
                const int p1 = p0 + 8;
                const int which = C >> 10;        // 1=K, 2=V
                const float* bp = (which == 1 ? bk : bv);
                const float bx = __ldg(&bp[h * 64 + d]);
                const float by = __ldg(&bp[h * 64 + d + 1]);
                const float v00 = acc[ms][nt][0] + bx, v01 = acc[ms][nt][1] + by;
                const float v10 = acc[ms][nt][2] + bx, v11 = acc[ms][nt][3] + by;

                if (which == 1) {
                    // plain compacted K [bh][pos][64]
                    __half* dst = g_kpl + (size_t)bh * S_ * 64 + d;
                    *(__half2*)(dst + (size_t)p0 * 64) = __floats2half2_rn(v00, v01);
                    *(__half2*)(dst + (size_t)p1 * 64) = __floats2half2_rn(v10, v11);
                } else {
                    // transposed compacted V [bh][d][pos]
                    __half* vb = g_vtp + (size_t)bh * 64 * S_;
                    vb[(size_t)d * S_ + p0]       = __float2half_rn(v00);
                    vb[(size_t)(d + 1) * S_ + p0] = __float2half_rn(v01);
                    vb[(size_t)d * S_ + p1]       = __float2half_rn(v10);
                    vb[(size_t)(d + 1) * S_ + p1] = __float2half_rn(v11);
                }
            }
        }
    }
}

// ---------------------------------------------------------------------------
// Output projection: [4096,1024] @ [1024,1024]. grid (32, 8), block 256.
// ---------------------------------------------------------------------------
__global__ __launch_bounds__(256, 2) void proj_kernel(
    const float* __restrict__ bo, float* __restrict__ out)
{
    const int m0 = blockIdx.x * 128;
    const int n0 = blockIdx.y * 128;

    float acc[4][4][4];
    gemm_main((const __half*)g_aoh + (size_t)(m0 + (threadIdx.x >> 1)) * 1024,
              g_woh + (size_t)n0 * 8, 1024, acc);

    const int tid  = threadIdx.x;
    const int warp = tid >> 5;
    const int lane = tid & 31;
    const int g    = lane >> 2;
    const int tig  = lane & 3;
    const int wm   = (warp >> 2) * 64;
    const int wn   = (warp & 3) * 32;

#pragma unroll
    for (int ms = 0; ms < 4; ms++) {
#pragma unroll
        for (int nt = 0; nt < 4; nt++) {
            const int r0 = m0 + wm + 16 * ms + g;
            const int c  = n0 + wn + 8 * nt + 2 * tig;
            const float bx = __ldg(&bo[c]);
            const float by = __ldg(&bo[c + 1]);
            *(float2*)(out + (size_t)r0 * 1024 + c) =
                make_float2(acc[ms][nt][0] + bx, acc[ms][nt][1] + by);
            *(float2*)(out + (size_t)(r0 + 8) * 1024 + c) =
                make_float2(acc[ms][nt][2] + bx, acc[ms][nt][3] + by);
        }
    }
}

// ---------------------------------------------------------------------------
// Flash attention (fp16 MMA). K/V fragments via ldmatrix.x4 from natural
// layouts (144B smem rows, conflict-free). P in registers; MMA row-sum;
// maskless mainloop; skip-rescale. 3-stage cp.async ring.
// ---------------------------------------------------------------------------
#define KV_ROW_B 144                       // bytes per smem row (64h + 8h pad)
#define TILE_WORDS (64 * KV_ROW_B / 4)     // 2304 words per K or V tile
#define ASTAGE (2 * TILE_WORDS)            // 4608 words per stage
#define ATTN_SMEM_BYTES (3 * ASTAGE * 4)

__global__ __launch_bounds__(256, 2) void attn_kernel()
{
    const int tid  = threadIdx.x;
    const int warp = tid >> 5;
    const int lane = tid & 31;
    const int g    = lane >> 2;
    const int tig  = lane & 3;

    const int bh = blockIdx.y;
    const int b  = bh >> 4;
    const int h  = bh & (H_ - 1);
    const int qbase = blockIdx.x * 128 + warp * 16;

    const int nv   = g_nv[b];
    const int npad = (nv + 63) & ~63;

    const __half* qp = g_qh + ((size_t)bh * S_ + qbase) * 64;
    uint32_t qf[4][4];
#pragma unroll
    for (int kk = 0; kk < 4; kk++) {
        qf[kk][0] = *(const uint32_t*)(qp + (size_t)g * 64 + kk * 16 + 2 * tig);
        qf[kk][1] = *(const uint32_t*)(qp + (size_t)(g + 8) * 64 + kk * 16 + 2 * tig);
        qf[kk][2] = *(const uint32_t*)(qp + (size_t)g * 64 + kk * 16 + 8 + 2 * tig);
        qf[kk][3] = *(const uint32_t*)(qp + (size_t)(g + 8) * 64 + kk * 16 + 8 + 2 * tig);
    }

    float oacc[8][4];
#pragma unroll
    for (int i = 0; i < 8; i++)
#pragma unroll
        for (int j = 0; j < 4; j++) oacc[i][j] = 0.f;
    float rm0 = -1e30f, rm1 = -1e30f;
    float rs0 = 0.f, rs1 = 0.f, rs2 = 0.f, rs3 = 0.f;
    const uint32_t ONE2 = 0x3C003C00u;

    const uint32_t sm = (uint32_t)__cvta_generic_to_shared(dynsmem);
    const __half* kpl_base = g_kpl + (size_t)bh * S_ * 64;
    const __half* vtp_base = g_vtp + (size_t)bh * 64 * S_;

    // per-lane ldmatrix row/half offsets (constant across tiles)
    const int lrow  = ((lane >> 4) << 3) + (lane & 7);   // row within 16-row pair
    const int lhalf = (lane >> 3) & 1;                   // second 8 cols
    const uint32_t foff = (uint32_t)(lrow * KV_ROW_B + lhalf * 16);

    auto copy_kv = [&](int kt, int st) {
        const uint32_t base = sm + (uint32_t)st * (ASTAGE * 4);
        const int row = tid >> 2, chunk = tid & 3;       // 64 rows x 4 chunks
        // K tile: rows = keys, 64 halves content
        const __half* srcK = kpl_base + (size_t)(kt + row) * 64 + chunk * 16;
        uint32_t dK = base + (uint32_t)(row * KV_ROW_B + chunk * 32);
        cpa16(dK, srcK);
        cpa16(dK + 16, srcK + 8);
        // V tile: rows = d, keys kt..kt+64 contiguous
        const __half* srcV = vtp_base + (size_t)row * S_ + kt + chunk * 16;
        uint32_t dV = base + TILE_WORDS * 4 + (uint32_t)(row * KV_ROW_B + chunk * 32);
        cpa16(dV, srcV);
        cpa16(dV + 16, srcV + 8);
        cp_commit();
    };

    copy_kv(0, 0);
    if (64 < npad) copy_kv(64, 1);

    const float* cm = g_cmask + b * S_;
    int st = 0;
#pragma unroll 1
    for (int kt = 0; kt < npad; kt += 64) {
        if (kt + 64 < npad) cp_wait<1>();
        else                cp_wait<0>();
        __syncthreads();
        if (kt + 128 < npad) {
            int nst = st + 2; if (nst >= 3) nst -= 3;
            copy_kv(kt + 128, nst);
        }

        const uint32_t kb = sm + (uint32_t)st * (ASTAGE * 4) + foff;
        const uint32_t vb = kb + TILE_WORDS * 4;

        // scores = Q @ K^T (K frags via ldmatrix.x4: 2 n-tiles per load)
        float sacc[8][4];
#pragma unroll
        for (int i = 0; i < 8; i++)
#pragma unroll
            for (int j = 0; j < 4; j++) sacc[i][j] = 0.f;
#pragma unroll
        for (int kk = 0; kk < 4; kk++) {
#pragma unroll
            for (int np = 0; np < 4; np++) {
                uint32_t c0, c1, c2, c3;
                LDSM4(c0, c1, c2, c3, kb + np * (16 * KV_ROW_B) + kk * 32);
                mma16(sacc[2*np][0], sacc[2*np][1], sacc[2*np][2], sacc[2*np][3],
                      qf[kk][0], qf[kk][1], qf[kk][2], qf[kk][3], c0, c1);
                mma16(sacc[2*np+1][0], sacc[2*np+1][1], sacc[2*np+1][2], sacc[2*np+1][3],
                      qf[kk][0], qf[kk][1], qf[kk][2], qf[kk][3], c2, c3);
            }
        }

        // mask only on the nv-boundary tile (CTA-uniform branch)
        float tm0 = -1e30f, tm1 = -1e30f;
        if (kt + 64 > nv) {
#pragma unroll
            for (int nt = 0; nt < 8; nt++) {
                const int mc = kt + nt * 8 + 2 * tig;
                const float m0v = __ldg(&cm[mc]);
                const float m1v = __ldg(&cm[mc + 1]);
                sacc[nt][0] += m0v;
                sacc[nt][1] += m1v;
                sacc[nt][2] += m0v;
                sacc[nt][3] += m1v;
                tm0 = fmaxf(tm0, fmaxf(sacc[nt][0], sacc[nt][1]));
                tm1 = fmaxf(tm1, fmaxf(sacc[nt][2], sacc[nt][3]));
            }
        } else {
#pragma unroll
            for (int nt = 0; nt < 8; nt++) {
                tm0 = fmaxf(tm0, fmaxf(sacc[nt][0], sacc[nt][1]));
                tm1 = fmaxf(tm1, fmaxf(sacc[nt][2], sacc[nt][3]));
            }
        }
        tm0 = fmaxf(tm0, __shfl_xor_sync(0xffffffff, tm0, 1));
        tm0 = fmaxf(tm0, __shfl_xor_sync(0xffffffff, tm0, 2));
        tm1 = fmaxf(tm1, __shfl_xor_sync(0xffffffff, tm1, 1));
        tm1 = fmaxf(tm1, __shfl_xor_sync(0xffffffff, tm1, 2));

        const float nm0 = fmaxf(rm0, tm0);
        const float nm1 = fmaxf(rm1, tm1);
        if (__any_sync(0xffffffffu, (nm0 > rm0) || (nm1 > rm1))) {
            const float c0 = exp2f(rm0 - nm0);
            const float c1 = exp2f(rm1 - nm1);
            rs0 *= c0; rs1 *= c0; rs2 *= c1; rs3 *= c1;
#pragma unroll
            for (int nt = 0; nt < 8; nt++) {
                oacc[nt][0] *= c0; oacc[nt][1] *= c0;
                oacc[nt][2] *= c1; oacc[nt][3] *= c1;
            }
        }
        rm0 = nm0; rm1 = nm1;

        // P = exp2(s - m) as packed fp16 pairs
        uint32_t pf[8][2];
#pragma unroll
        for (int nt = 0; nt < 8; nt++) {
            pf[nt][0] = h2u(h2exp2(__floats2half2_rn(sacc[nt][0] - nm0,
                                                     sacc[nt][1] - nm0)));
            pf[nt][1] = h2u(h2exp2(__floats2half2_rn(sacc[nt][2] - nm1,
                                                     sacc[nt][3] - nm1)));
        }

        // O += P @ V (V frags via ldmatrix.x4), rowsums += P @ ones
#pragma unroll
        for (int kk = 0; kk < 4; kk++) {
            const uint32_t a0 = pf[2 * kk][0];
            const uint32_t a1 = pf[2 * kk][1];
            const uint32_t a2 = pf[2 * kk + 1][0];
            const uint32_t a3 = pf[2 * kk + 1][1];
            mma16(rs0, rs1, rs2, rs3, a0, a1, a2, a3, ONE2, ONE2);
#pragma unroll
            for (int np = 0; np < 4; np++) {
                uint32_t c0, c1, c2, c3;
                LDSM4(c0, c1, c2, c3, vb + np * (16 * KV_ROW_B) + kk * 32);
                mma16(oacc[2*np][0], oacc[2*np][1], oacc[2*np][2], oacc[2*np][3],
                      a0, a1, a2, a3, c0, c1);
                mma16(oacc[2*np+1][0], oacc[2*np+1][1], oacc[2*np+1][2], oacc[2*np+1][3],
                      a0, a1, a2, a3, c2, c3);
            }
        }
        st = (st + 1 == 3) ? 0 : st + 1;
    }

    const float inv0 = 1.f / rs0;
    const float inv1 = 1.f / rs2;

    // write attention output in permuted fp16 layout for proj (row = 512 words)
    const size_t row0 = (size_t)b * S_ + qbase + g;
#pragma unroll
    for (int nt = 0; nt < 8; nt++) {
        const int C = h * 64 + nt * 8 + 2 * tig;
        const int j = C & 15;
        const int w = (C >> 4) * 8 + (j & 6) + (j >> 3);
        g_aoh[row0 * 512 + w] =
            h2u(__floats2half2_rn(oacc[nt][0] * inv0, oacc[nt][1] * inv0));
        g_aoh[(row0 + 8) * 512 + w] =
            h2u(__floats2half2_rn(oacc[nt][2] * inv1, oacc[nt][3] * inv1));
    }
}

// ---------------------------------------------------------------------------
extern "C" void kernel_launch(void* const* d_in, const int* in_sizes, int n_in,
                              void* d_out, int out_size)
{
    const float* x    = (const float*)d_in[0];
    const int*   mask = (const int*)  d_in[1];
    const float* wq   = (const float*)d_in[2];
    const float* bq   = (const float*)d_in[3];
    const float* wk   = (const float*)d_in[4];
    const float* bk   = (const float*)d_in[5];
    const float* wv   = (const float*)d_in[6];
    const float* bv   = (const float*)d_in[7];
    const float* wo   = (const float*)d_in[8];
    const float* bo   = (const float*)d_in[9];
    float* out = (float*)d_out;

    static bool attrs_set = false;
    if (!attrs_set) {
        cudaFuncSetAttribute(qkv2_kernel, cudaFuncAttributeMaxDynamicSharedMemorySize, GEMM_SMEM_BYTES);
        cudaFuncSetAttribute(proj_kernel, cudaFuncAttributeMaxDynamicSharedMemorySize, GEMM_SMEM_BYTES);
        cudaFuncSetAttribute(attn_kernel, cudaFuncAttributeMaxDynamicSharedMemorySize, ATTN_SMEM_BYTES);
        attrs_set = true;
    }

    scan_mask<<<B_, 1024>>>(mask);
    prep_all<<<2048, 256>>>(x, wq, wk, wv, wo);

    dim3 gqkv(S_ * B_ / 128, 24);
    qkv2_kernel<<<gqkv, 256, GEMM_SMEM_BYTES>>>(bq, bk, bv);

    dim3 g2(S_ / 128, BH_);
    attn_kernel<<<g2, 256, ATTN_SMEM_BYTES>>>();

    dim3 g3((B_ * S_) / 128, E_ / 128);
    proj_kernel<<<g3, 256, GEMM_SMEM_BYTES>>>(bo, out);
}

// round 17
// speedup vs baseline: 1.0301x; 1.0301x over previous
#include <cuda_runtime.h>
#include <cuda_fp16.h>
#include <math.h>
#include <stdint.h>

#define B_  2
#define S_  2048
#define E_  1024
#define H_  16
#define DH_ 64
#define BH_ (B_*H_)

// ---------------------------------------------------------------------------
// Global scratch (allocation-free rule). Zero-initialized at module load;
// cells never written stay zero on every replay (writes are deterministic).
// ---------------------------------------------------------------------------
__device__ __half    g_xh [(size_t)B_*S_*E_];           // x fp16, 16k-permuted [4096][1024]
__device__ uint32_t  g_wch[(size_t)64*3072*8];          // QKV W frag: [k16][n][8 words]
__device__ uint32_t  g_woh[(size_t)64*1024*8];          // wo frag:    [k16][n][8 words]
__device__ __half    g_qh [(size_t)BH_*S_*DH_];         // plain [bh][S][64], pre-scaled
__device__ uint32_t  g_kc [(size_t)BH_*4*S_*8];         // compact K frag [bh][d16][key][8w]
__device__ __half    g_vc [(size_t)BH_*(S_/16)*DH_*16]; // compact V frag [bh][k16][d][16h]
__device__ uint32_t  g_aoh[(size_t)B_*S_*512];          // attn out fp16 perm [4096][512w]
__device__ int       g_perm[(size_t)B_*S_];             // compact pos -> s
__device__ int       g_nv[B_];
__device__ float     g_cmask[(size_t)B_*S_];            // 0 or -1e9*log2e

// ---------------------------------------------------------------------------
// helpers
// ---------------------------------------------------------------------------
__device__ __forceinline__ int posf(int j) {            // 16-k block permutation
    return ((j & 6) + (j >> 3)) * 2 + (j & 1);
}

__device__ __forceinline__ void mma16(float& d0, float& d1, float& d2, float& d3,
                                      uint32_t a0, uint32_t a1, uint32_t a2, uint32_t a3,
                                      uint32_t b0, uint32_t b1) {
    asm volatile(
        "mma.sync.aligned.m16n8k16.row.col.f32.f16.f16.f32 "
        "{%0,%1,%2,%3}, {%4,%5,%6,%7}, {%8,%9}, {%0,%1,%2,%3};"
        : "+f"(d0), "+f"(d1), "+f"(d2), "+f"(d3)
        : "r"(a0), "r"(a1), "r"(a2), "r"(a3), "r"(b0), "r"(b1));
}

__device__ __forceinline__ void cpa16(uint32_t dst_smem, const void* src) {
    asm volatile("cp.async.cg.shared.global [%0], [%1], 16;\n"
                 :: "r"(dst_smem), "l"(src));
}
__device__ __forceinline__ void cp_commit() {
    asm volatile("cp.async.commit_group;\n");
}
template<int N> __device__ __forceinline__ void cp_wait() {
    asm volatile("cp.async.wait_group %0;\n" :: "n"(N));
}

__device__ __forceinline__ uint32_t h2u(__half2 h) {
    return *reinterpret_cast<uint32_t*>(&h);
}

// ---------------------------------------------------------------------------
// Unified prep: blocks [0,1024) xh, [1024,1792) wc, [1792,2048) wo,
// [2048,2048+B_) mask scan (256-thread variant). One launch total.
// ---------------------------------------------------------------------------
__global__ __launch_bounds__(256) void prep_all(
    const float* __restrict__ x,
    const float* __restrict__ wq, const float* __restrict__ wk,
    const float* __restrict__ wv, const float* __restrict__ wo,
    const int* __restrict__ mask)
{
    const int blk = blockIdx.x;
    const int tid = threadIdx.x;

    if (blk < 1024) {                                  // ---- x -> g_xh
        int i = blk * 256 + tid;
        int row = i >> 6, grp = i & 63;
        const float* s = x + (size_t)row * 1024 + grp * 16;
        float v[16];
#pragma unroll
        for (int j = 0; j < 4; j++) {
            float4 t = *(const float4*)(s + j * 4);
            v[j*4] = t.x; v[j*4+1] = t.y; v[j*4+2] = t.z; v[j*4+3] = t.w;
        }
        __align__(16) __half o[16];
#pragma unroll
        for (int j = 0; j < 16; j++) o[posf(j)] = __float2half_rn(v[j]);
        *(uint4*)(g_xh + (size_t)row * 1024 + grp * 16)     = ((uint4*)o)[0];
        *(uint4*)(g_xh + (size_t)row * 1024 + grp * 16 + 8) = ((uint4*)o)[1];
    } else if (blk < 1792) {                           // ---- qkv weights
        int i = (blk - 1024) * 256 + tid;              // i = k16*3072 + n
        int k16 = i / 3072;
        int n = i - k16 * 3072;
        int which = n >> 10;
        int h = (n >> 6) & 15;
        int d = n & 63;
        const float* w = (which == 0 ? wq : (which == 1 ? wk : wv))
                         + ((size_t)h * 1024 + k16 * 16) * 64 + d;
        __align__(16) __half o[16];
#pragma unroll
        for (int j = 0; j < 16; j++) o[posf(j)] = __float2half_rn(w[j * 64]);
        uint32_t* dst = g_wch + ((size_t)k16 * 3072 + n) * 8;
        *(uint4*)dst       = ((uint4*)o)[0];
        *(uint4*)(dst + 4) = ((uint4*)o)[1];
    } else if (blk < 2048) {                           // ---- wo
        int i = (blk - 1792) * 256 + tid;
        int k16 = i >> 10;
        int n = i & 1023;
        __align__(16) __half o[16];
#pragma unroll
        for (int j = 0; j < 16; j++)
            o[posf(j)] = __float2half_rn(wo[(size_t)(k16 * 16 + j) * 1024 + n]);
        uint32_t* dst = g_woh + ((size_t)k16 * 1024 + n) * 8;
        *(uint4*)dst       = ((uint4*)o)[0];
        *(uint4*)(dst + 4) = ((uint4*)o)[1];
    } else {                                           // ---- mask scan (batch b)
        __shared__ int buf[2][256];
        const int b = blk - 2048;
        const int base = b * 2048 + tid * 8;
        int m[8];
        int sum = 0;
#pragma unroll
        for (int j = 0; j < 8; j++) {
            m[j] = (mask[base + j] != 0);
            sum += m[j];
        }
        buf[0][tid] = sum;
        __syncthreads();
        int src = 0;
        for (int off = 1; off < 256; off <<= 1) {
            int v = buf[src][tid];
            if (tid >= off) v += buf[src][tid - off];
            buf[src ^ 1][tid] = v;
            src ^= 1;
            __syncthreads();
        }
        const int nv = buf[src][255];
        int pos = buf[src][tid] - sum;                 // exclusive prefix
#pragma unroll
        for (int j = 0; j < 8; j++)
            if (m[j]) g_perm[b * 2048 + pos++] = tid * 8 + j;
        if (tid == 0) g_nv[b] = nv;
        const float MBv = -1.4426950408889634e9f;
#pragma unroll
        for (int j = 0; j < 8; j++)
            g_cmask[base + j] = (tid * 8 + j < nv) ? 0.f : MBv;
    }
}

// ---------------------------------------------------------------------------
// GEMM mainloop (fp16): 128x128 tile, 256 threads (8 warps, warp tile 64x32),
// k-step 32 halves, 4-stage cp.async ring. A given as the thread's own row.
// ---------------------------------------------------------------------------
#define LDA 24
#define A_BUF (128*LDA)
#define B_BUF 2048
#define STAGE_WORDS (A_BUF + B_BUF)
#define GEMM_SMEM_BYTES (4 * STAGE_WORDS * 4)

extern __shared__ uint32_t dynsmem[];

__device__ __forceinline__ void gemm_main(
    const __half* __restrict__ Arow,
    const uint32_t* __restrict__ Bw,
    int nTot,
    float acc[4][4][4])
{
    const int tid  = threadIdx.x;
    const int warp = tid >> 5;
    const int lane = tid & 31;
    const int g    = lane >> 2;
    const int tig  = lane & 3;
    const int wm   = (warp >> 2) * 64;
    const int wn   = (warp & 3) * 32;

#pragma unroll
    for (int ms = 0; ms < 4; ms++)
#pragma unroll
        for (int nt = 0; nt < 4; nt++)
#pragma unroll
            for (int r = 0; r < 4; r++) acc[ms][nt][r] = 0.f;

    const uint32_t sm = (uint32_t)__cvta_generic_to_shared(dynsmem);

    const int arow = tid >> 1;
    const int apart = tid & 1;
    const int bblk = tid >> 7;
    const int bn   = tid & 127;

    auto copy_tile = [&](int k0, int st) {
        const uint32_t base = sm + (uint32_t)st * (STAGE_WORDS * 4);
        uint32_t dA = base + (uint32_t)arow * (LDA * 4) + (uint32_t)apart * 32;
        const __half* srcA = Arow + k0 + apart * 16;
        cpa16(dA, srcA);
        cpa16(dA + 16, srcA + 8);
        uint32_t dB = base + A_BUF * 4 + (uint32_t)(bblk * 1024 + bn * 8) * 4;
        const uint32_t* srcB = Bw + ((size_t)((k0 >> 4) + bblk) * nTot + bn) * 8;
        cpa16(dB, srcB);
        cpa16(dB + 16, srcB + 4);
        cp_commit();
    };

    copy_tile(0, 0);
    copy_tile(32, 1);
    copy_tile(64, 2);

    int st = 0;
#pragma unroll 1
    for (int k0 = 0; k0 < 1024; k0 += 32) {
        if (k0 + 64 < 1024)      cp_wait<2>();
        else if (k0 + 32 < 1024) cp_wait<1>();
        else                     cp_wait<0>();
        __syncthreads();
        if (k0 + 96 < 1024) {
            int nst = st + 3; if (nst >= 4) nst -= 4;
            copy_tile(k0 + 96, nst);
        }

        const uint32_t* A  = dynsmem + st * STAGE_WORDS;
        const uint32_t* Bt = A + A_BUF;
#pragma unroll
        for (int kk = 0; kk < 2; kk++) {
            uint32_t af[4][4];
#pragma unroll
            for (int ms = 0; ms < 4; ms++) {
                const uint32_t* ap = A + (wm + 16 * ms + g) * LDA + kk * 8 + 2 * tig;
                uint2 lo = *(const uint2*)ap;
                uint2 hi = *(const uint2*)(ap + 8 * LDA);
                af[ms][0] = lo.x; af[ms][1] = hi.x; af[ms][2] = lo.y; af[ms][3] = hi.y;
            }
#pragma unroll
            for (int nt = 0; nt < 4; nt++) {
                uint2 b = *(const uint2*)(Bt + kk * 1024 + (wn + 8 * nt + g) * 8 + 2 * tig);
#pragma unroll
                for (int ms = 0; ms < 4; ms++)
                    mma16(acc[ms][nt][0], acc[ms][nt][1], acc[ms][nt][2], acc[ms][nt][3],
                          af[ms][0], af[ms][1], af[ms][2], af[ms][3], b.x, b.y);
            }
        }
        st = (st + 1 == 4) ? 0 : st + 1;
    }
}

// ---------------------------------------------------------------------------
// Combined Q + KV projections in ONE launch. grid (32, 24), block 256.
//   y in [0,8):  Q path   — A rows from g_xh directly, cols [0,1024)
//   y in [8,24): KV path  — A rows gathered from g_xh via g_perm,
//                           cols [1024,3072), early-exit past npad128(b)
// ---------------------------------------------------------------------------
__global__ __launch_bounds__(256, 2) void qkv2_kernel(
    const float* __restrict__ bq, const float* __restrict__ bk,
    const float* __restrict__ bv)
{
    const int m0 = blockIdx.x * 128;
    const int ny = blockIdx.y;
    const int b  = m0 >> 11;
    const bool isQ = (ny < 8);

    const int nv = g_nv[b];
    if (!isQ) {
        const int npad128 = (nv + 127) & ~127;
        if ((m0 & 2047) >= npad128) return;
    }

    const int n0 = isQ ? ny * 128 : 1024 + (ny - 8) * 128;

    const int tid  = threadIdx.x;
    const __half* Arow;
    if (isQ) {
        Arow = g_xh + (size_t)(m0 + (tid >> 1)) * 1024;
    } else {
        const int p = (m0 & 2047) + (tid >> 1);
        const int srow = (p < nv) ? g_perm[b * 2048 + p] : 0;
        Arow = g_xh + ((size_t)b * 2048 + srow) * 1024;
    }

    float acc[4][4][4];
    gemm_main(Arow, g_wch + (size_t)n0 * 8, 3072, acc);

    const int warp = tid >> 5;
    const int lane = tid & 31;
    const int g    = lane >> 2;
    const int tig  = lane & 3;
    const int wm   = (warp >> 2) * 64;
    const int wn   = (warp & 3) * 32;

    const float SC = 0.18033688011112158f;   // (1/8) * log2(e)

#pragma unroll
    for (int ms = 0; ms < 4; ms++) {
#pragma unroll
        for (int nt = 0; nt < 4; nt++) {
            const int C = n0 + wn + 8 * nt + 2 * tig;
            const int h = (C >> 6) & 15;
            const int d = C & 63;
            const int bh = b * 16 + h;

            if (isQ) {
                const int r0 = m0 + wm + 16 * ms + g;
                const int s0 = r0 & 2047;
                const int s1 = s0 + 8;
                const float bx = __ldg(&bq[C]);
                const float by = __ldg(&bq[C + 1]);
                __half* dst = g_qh + (size_t)bh * S_ * 64;
                *(__half2*)(dst + (size_t)s0 * 64 + d) =
                    __floats2half2_rn((acc[ms][nt][0] + bx) * SC,
                                      (acc[ms][nt][1] + by) * SC);
                *(__half2*)(dst + (size_t)s1 * 64 + d) =
                    __floats2half2_rn((acc[ms][nt][2] + bx) * SC,
                                      (acc[ms][nt][3] + by) * SC);
            } else {
                const int p0 = (m0 & 2047) + wm + 16 * ms + g;
                const int p1 = p0 + 8;
                const int which = C >> 10;        // 1=K, 2=V
                const float* bp = (which == 1 ? bk : bv);
                const float bx = __ldg(&bp[h * 64 + d]);
                const float by = __ldg(&bp[h * 64 + d + 1]);
                const float v00 = acc[ms][nt][0] + bx, v01 = acc[ms][nt][1] + by;
                const float v10 = acc[ms][nt][2] + bx, v11 = acc[ms][nt][3] + by;

                if (which == 1) {
                    const int j = d & 15;
                    const int word = (j & 6) + (j >> 3);
                    uint32_t* cellb = g_kc + ((size_t)(bh * 4 + (d >> 4)) * S_) * 8 + word;
                    cellb[(size_t)p0 * 8] = h2u(__floats2half2_rn(v00, v01));
                    cellb[(size_t)p1 * 8] = h2u(__floats2half2_rn(v10, v11));
                } else {
                    __half* vb = g_vc + (size_t)bh * (S_ / 16) * 1024;
                    __half* cell0 = vb + ((size_t)(p0 >> 4) * 64) * 16 + posf(p0 & 15);
                    cell0[(size_t)d * 16]       = __float2half_rn(v00);
                    cell0[(size_t)(d + 1) * 16] = __float2half_rn(v01);
                    __half* cell1 = vb + ((size_t)(p1 >> 4) * 64) * 16 + posf(p1 & 15);
                    cell1[(size_t)d * 16]       = __float2half_rn(v10);
                    cell1[(size_t)(d + 1) * 16] = __float2half_rn(v11);
                }
            }
        }
    }
}

// ---------------------------------------------------------------------------
// Output projection: [4096,1024] @ [1024,1024]. grid (32, 8), block 256.
// ---------------------------------------------------------------------------
__global__ __launch_bounds__(256, 2) void proj_kernel(
    const float* __restrict__ bo, float* __restrict__ out)
{
    const int m0 = blockIdx.x * 128;
    const int n0 = blockIdx.y * 128;

    float acc[4][4][4];
    gemm_main((const __half*)g_aoh + (size_t)(m0 + (threadIdx.x >> 1)) * 1024,
              g_woh + (size_t)n0 * 8, 1024, acc);

    const int tid  = threadIdx.x;
    const int warp = tid >> 5;
    const int lane = tid & 31;
    const int g    = lane >> 2;
    const int tig  = lane & 3;
    const int wm   = (warp >> 2) * 64;
    const int wn   = (warp & 3) * 32;

#pragma unroll
    for (int ms = 0; ms < 4; ms++) {
#pragma unroll
        for (int nt = 0; nt < 4; nt++) {
            const int r0 = m0 + wm + 16 * ms + g;
            const int c  = n0 + wn + 8 * nt + 2 * tig;
            const float bx = __ldg(&bo[c]);
            const float by = __ldg(&bo[c + 1]);
            *(float2*)(out + (size_t)r0 * 1024 + c) =
                make_float2(acc[ms][nt][0] + bx, acc[ms][nt][1] + by);
            *(float2*)(out + (size_t)(r0 + 8) * 1024 + c) =
                make_float2(acc[ms][nt][2] + bx, acc[ms][nt][3] + by);
        }
    }
}

// ---------------------------------------------------------------------------
// Flash attention (fp16 MMA). P in registers; MMA row-sum denominator;
// maskless mainloop; skip-rescale. 3-stage cp.async ring. (r15 proven form)
// ---------------------------------------------------------------------------
#define ASTAGE 4096
#define ATTN_SMEM_BYTES (3 * ASTAGE * 4)

__global__ __launch_bounds__(256, 2) void attn_kernel()
{
    const int tid  = threadIdx.x;
    const int warp = tid >> 5;
    const int lane = tid & 31;
    const int g    = lane >> 2;
    const int tig  = lane & 3;

    const int bh = blockIdx.y;
    const int b  = bh >> 4;
    const int h  = bh & (H_ - 1);
    const int qbase = blockIdx.x * 128 + warp * 16;

    const int nv   = g_nv[b];
    const int npad = (nv + 63) & ~63;

    const __half* qp = g_qh + ((size_t)bh * S_ + qbase) * 64;
    uint32_t qf[4][4];
#pragma unroll
    for (int kk = 0; kk < 4; kk++) {
        qf[kk][0] = *(const uint32_t*)(qp + (size_t)g * 64 + kk * 16 + 2 * tig);
        qf[kk][1] = *(const uint32_t*)(qp + (size_t)(g + 8) * 64 + kk * 16 + 2 * tig);
        qf[kk][2] = *(const uint32_t*)(qp + (size_t)g * 64 + kk * 16 + 8 + 2 * tig);
        qf[kk][3] = *(const uint32_t*)(qp + (size_t)(g + 8) * 64 + kk * 16 + 8 + 2 * tig);
    }

    float oacc[8][4];
#pragma unroll
    for (int i = 0; i < 8; i++)
#pragma unroll
        for (int j = 0; j < 4; j++) oacc[i][j] = 0.f;
    float rm0 = -1e30f, rm1 = -1e30f;
    float rs0 = 0.f, rs1 = 0.f, rs2 = 0.f, rs3 = 0.f;   // rowsum MMA accum
    const uint32_t ONE2 = 0x3C003C00u;                  // fp16 {1.0, 1.0}

    const uint32_t sm = (uint32_t)__cvta_generic_to_shared(dynsmem);
    const uint32_t* kc_base = g_kc + (size_t)bh * 4 * S_ * 8;
    const uint32_t* vc_base = (const uint32_t*)g_vc + (size_t)bh * (S_ / 16) * 512;

    auto copy_kv = [&](int kt, int st) {
        const uint32_t base = sm + (uint32_t)st * (ASTAGE * 4);
        const int blk = tid >> 6, kx = tid & 63;
        const uint32_t* srcK = kc_base + ((size_t)blk * S_ + kt + kx) * 8;
        uint32_t dK = base + (uint32_t)(blk * 512 + kx * 8) * 4;
        cpa16(dK, srcK);
        cpa16(dK + 16, srcK + 4);
        const uint32_t* srcV = vc_base + (((size_t)(kt >> 4) + blk) * 64 + kx) * 8;
        uint32_t dV = base + 2048 * 4 + (uint32_t)(blk * 512 + kx * 8) * 4;
        cpa16(dV, srcV);
        cpa16(dV + 16, srcV + 4);
        cp_commit();
    };

    copy_kv(0, 0);
    if (64 < npad) copy_kv(64, 1);

    const float* cm = g_cmask + b * S_;
    int st = 0;
#pragma unroll 1
    for (int kt = 0; kt < npad; kt += 64) {
        if (kt + 64 < npad) cp_wait<1>();
        else                cp_wait<0>();
        __syncthreads();
        if (kt + 128 < npad) {
            int nst = st + 2; if (nst >= 3) nst -= 3;
            copy_kv(kt + 128, nst);
        }

        const uint32_t* Kb = dynsmem + st * ASTAGE;
        const uint32_t* Vb = Kb + 2048;

        float sacc[8][4];
#pragma unroll
        for (int i = 0; i < 8; i++)
#pragma unroll
            for (int j = 0; j < 4; j++) sacc[i][j] = 0.f;
#pragma unroll
        for (int kk = 0; kk < 4; kk++) {
#pragma unroll
            for (int nt = 0; nt < 8; nt++) {
                uint2 bb = *(const uint2*)(Kb + kk * 512 + (nt * 8 + g) * 8 + 2 * tig);
                mma16(sacc[nt][0], sacc[nt][1], sacc[nt][2], sacc[nt][3],
                      qf[kk][0], qf[kk][1], qf[kk][2], qf[kk][3], bb.x, bb.y);
            }
        }

        // mask only on the nv-boundary tile (CTA-uniform branch)
        float tm0 = -1e30f, tm1 = -1e30f;
        if (kt + 64 > nv) {
#pragma unroll
            for (int nt = 0; nt < 8; nt++) {
                const int mc = kt + nt * 8 + 2 * tig;
                const float m0v = __ldg(&cm[mc]);
                const float m1v = __ldg(&cm[mc + 1]);
                sacc[nt][0] += m0v;
                sacc[nt][1] += m1v;
                sacc[nt][2] += m0v;
                sacc[nt][3] += m1v;
                tm0 = fmaxf(tm0, fmaxf(sacc[nt][0], sacc[nt][1]));
                tm1 = fmaxf(tm1, fmaxf(sacc[nt][2], sacc[nt][3]));
            }
        } else {
#pragma unroll
            for (int nt = 0; nt < 8; nt++) {
                tm0 = fmaxf(tm0, fmaxf(sacc[nt][0], sacc[nt][1]));
                tm1 = fmaxf(tm1, fmaxf(sacc[nt][2], sacc[nt][3]));
            }
        }
        tm0 = fmaxf(tm0, __shfl_xor_sync(0xffffffff, tm0, 1));
        tm0 = fmaxf(tm0, __shfl_xor_sync(0xffffffff, tm0, 2));
        tm1 = fmaxf(tm1, __shfl_xor_sync(0xffffffff, tm1, 1));
        tm1 = fmaxf(tm1, __shfl_xor_sync(0xffffffff, tm1, 2));

        const float nm0 = fmaxf(rm0, tm0);
        const float nm1 = fmaxf(rm1, tm1);
        if (__any_sync(0xffffffffu, (nm0 > rm0) || (nm1 > rm1))) {
            const float c0 = exp2f(rm0 - nm0);
            const float c1 = exp2f(rm1 - nm1);
            rs0 *= c0; rs1 *= c0; rs2 *= c1; rs3 *= c1;
#pragma unroll
            for (int nt = 0; nt < 8; nt++) {
                oacc[nt][0] *= c0; oacc[nt][1] *= c0;
                oacc[nt][2] *= c1; oacc[nt][3] *= c1;
            }
        }
        rm0 = nm0; rm1 = nm1;

        // P = exp2(s - m) as packed fp16 pairs
        uint32_t pf[8][2];
#pragma unroll
        for (int nt = 0; nt < 8; nt++) {
            pf[nt][0] = h2u(h2exp2(__floats2half2_rn(sacc[nt][0] - nm0,
                                                     sacc[nt][1] - nm0)));
            pf[nt][1] = h2u(h2exp2(__floats2half2_rn(sacc[nt][2] - nm1,
                                                     sacc[nt][3] - nm1)));
        }

        // O += P @ V, and rowsums += P @ ones (tensor-core denominator)
#pragma unroll
        for (int kk = 0; kk < 4; kk++) {
            const uint32_t a0 = pf[2 * kk][0];
            const uint32_t a1 = pf[2 * kk][1];
            const uint32_t a2 = pf[2 * kk + 1][0];
            const uint32_t a3 = pf[2 * kk + 1][1];
            mma16(rs0, rs1, rs2, rs3, a0, a1, a2, a3, ONE2, ONE2);
#pragma unroll
            for (int nt = 0; nt < 8; nt++) {
                uint2 bb = *(const uint2*)(Vb + kk * 512 + (nt * 8 + g) * 8 + 2 * tig);
                mma16(oacc[nt][0], oacc[nt][1], oacc[nt][2], oacc[nt][3],
                      a0, a1, a2, a3, bb.x, bb.y);
            }
        }
        st = (st + 1 == 3) ? 0 : st + 1;
    }

    const float inv0 = 1.f / rs0;
    const float inv1 = 1.f / rs2;

    // write attention output in permuted fp16 layout for proj (row = 512 words)
    const size_t row0 = (size_t)b * S_ + qbase + g;
#pragma unroll
    for (int nt = 0; nt < 8; nt++) {
        const int C = h * 64 + nt * 8 + 2 * tig;
        const int j = C & 15;
        const int w = (C >> 4) * 8 + (j & 6) + (j >> 3);
        g_aoh[row0 * 512 + w] =
            h2u(__floats2half2_rn(oacc[nt][0] * inv0, oacc[nt][1] * inv0));
        g_aoh[(row0 + 8) * 512 + w] =
            h2u(__floats2half2_rn(oacc[nt][2] * inv1, oacc[nt][3] * inv1));
    }
}

// ---------------------------------------------------------------------------
extern "C" void kernel_launch(void* const* d_in, const int* in_sizes, int n_in,
                              void* d_out, int out_size)
{
    const float* x    = (const float*)d_in[0];
    const int*   mask = (const int*)  d_in[1];
    const float* wq   = (const float*)d_in[2];
    const float* bq   = (const float*)d_in[3];
    const float* wk   = (const float*)d_in[4];
    const float* bk   = (const float*)d_in[5];
    const float* wv   = (const float*)d_in[6];
    const float* bv   = (const float*)d_in[7];
    const float* wo   = (const float*)d_in[8];
    const float* bo   = (const float*)d_in[9];
    float* out = (float*)d_out;

    static bool attrs_set = false;
    if (!attrs_set) {
        cudaFuncSetAttribute(qkv2_kernel, cudaFuncAttributeMaxDynamicSharedMemorySize, GEMM_SMEM_BYTES);
        cudaFuncSetAttribute(proj_kernel, cudaFuncAttributeMaxDynamicSharedMemorySize, GEMM_SMEM_BYTES);
        cudaFuncSetAttribute(attn_kernel, cudaFuncAttributeMaxDynamicSharedMemorySize, ATTN_SMEM_BYTES);
        attrs_set = true;
    }

    prep_all<<<2048 + B_, 256>>>(x, wq, wk, wv, wo, mask);

    dim3 gqkv(S_ * B_ / 128, 24);
    qkv2_kernel<<<gqkv, 256, GEMM_SMEM_BYTES>>>(bq, bk, bv);

    dim3 g2(S_ / 128, BH_);
    attn_kernel<<<g2, 256, ATTN_SMEM_BYTES>>>();

    dim3 g3((B_ * S_) / 128, E_ / 128);
    proj_kernel<<<g3, 256, GEMM_SMEM_BYTES>>>(bo, out);
}